// round 1
// baseline (speedup 1.0000x reference)
#include <cuda_runtime.h>
#include <math.h>
#include <limits.h>

#define NN  20000
#define MM  4
#define DD  64
#define NHH 4
#define NLL 2
#define EE  320000
#define ETOT (EE + NN)
#define FF  (NHH * DD)   // 256

// ------------------------- scratch (static device globals) -------------------
__device__ float g_x[2][NN * DD];        // ping-pong node features
__device__ float g_xl[NN * FF];          // source transform
__device__ float g_xr[NN * FF];          // target transform
__device__ float g_logit[(size_t)ETOT * NHH];  // logits -> exp values
__device__ int   g_mx[NN * NHH];         // segment max (ordered-int encoding)
__device__ float g_denom[NN * NHH];      // segment sum of exp
__device__ float g_agg[NN * DD];         // aggregated output (head-mean folded)

__device__ __forceinline__ float gelu_exact(float v) {
    return 0.5f * v * (1.0f + erff(v * 0.70710678118654752f));
}

// ------------------------- K1: encoders + initial fusion ---------------------
// one block (64 threads) per node
__global__ void k_encode(const float* __restrict__ xin,
                         const float* __restrict__ ew1, const float* __restrict__ eb1,
                         const float* __restrict__ ew2, const float* __restrict__ eb2,
                         const float* __restrict__ fw,  const float* __restrict__ fb,
                         float* __restrict__ z_out)
{
    int n = blockIdx.x;
    int tid = threadIdx.x;           // 0..63
    __shared__ float sh_h[MM * 32];
    __shared__ float sh_zm[DD];
    __shared__ float sh_x[MM];
    if (tid < MM) sh_x[tid] = xin[n * MM + tid];
    __syncthreads();
    for (int idx = tid; idx < MM * 32; idx += 64) {
        int m = idx >> 5;
        float v = sh_x[m] * ew1[idx] + eb1[idx];
        sh_h[idx] = gelu_exact(v);
    }
    __syncthreads();
    int d = tid;
    float zm = 0.f;
    #pragma unroll
    for (int m = 0; m < MM; m++) {
        const float* w  = ew2 + ((size_t)(m * DD + d)) * 32;
        const float* hh = sh_h + m * 32;
        float acc = eb2[m * DD + d];
        #pragma unroll
        for (int j = 0; j < 32; j++) acc += hh[j] * w[j];
        z_out[(size_t)n * MM * DD + m * DD + d] = acc;
        zm += acc;
    }
    sh_zm[d] = zm * (1.0f / MM);
    __syncthreads();
    float acc = fb[d];
    const float* w = fw + d * DD;
    #pragma unroll
    for (int k = 0; k < DD; k++) acc += sh_zm[k] * w[k];
    g_x[0][n * DD + d] = acc;
}

// ------------------------- per-layer init ------------------------------------
__global__ void k_init()
{
    int i = blockIdx.x * blockDim.x + threadIdx.x;
    if (i < NN * NHH) { g_mx[i] = INT_MIN; g_denom[i] = 0.f; }
    if (i < NN * DD)  g_agg[i] = 0.f;
}

// ------------------------- K2: xl = x@Wl^T+bl, xr = x@Wr^T+br ----------------
// 8 nodes per block, 256 threads (one output channel each)
__global__ void k_lin(int xsel,
                      const float* __restrict__ wl, const float* __restrict__ bl,
                      const float* __restrict__ wr, const float* __restrict__ br)
{
    __shared__ float xs[8 * DD];
    int nb = blockIdx.x * 8;
    int tid = threadIdx.x;           // 0..255
    const float* xsrc = g_x[xsel];
    for (int i = tid; i < 8 * DD; i += 256) xs[i] = xsrc[nb * DD + i];
    __syncthreads();
    int o = tid;
    float aL[8], aR[8];
    #pragma unroll
    for (int i = 0; i < 8; i++) { aL[i] = 0.f; aR[i] = 0.f; }
    const float* wlo = wl + o * DD;
    const float* wro = wr + o * DD;
    for (int k = 0; k < DD; k++) {
        float w1 = wlo[k], w2 = wro[k];
        #pragma unroll
        for (int i = 0; i < 8; i++) {
            float xv = xs[i * DD + k];
            aL[i] += xv * w1;
            aR[i] += xv * w2;
        }
    }
    float blv = bl[o], brv = br[o];
    #pragma unroll
    for (int i = 0; i < 8; i++) {
        g_xl[(size_t)(nb + i) * FF + o] = aL[i] + blv;
        g_xr[(size_t)(nb + i) * FF + o] = aR[i] + brv;
    }
}

// ------------------------- K3: edge logits + segment max ---------------------
// one warp per edge
__global__ void k_logit(const int* __restrict__ src, const int* __restrict__ dst,
                        const float* __restrict__ att)
{
    int widx = (blockIdx.x * blockDim.x + threadIdx.x) >> 5;
    int lane = threadIdx.x & 31;
    if (widx >= ETOT) return;
    int s, t;
    if (widx < EE) { s = src[widx]; t = dst[widx]; }
    else           { s = t = widx - EE; }
    const float* xls = g_xl + (size_t)s * FF;
    const float* xrt = g_xr + (size_t)t * FF;
    float ph[NHH];
    #pragma unroll
    for (int h = 0; h < NHH; h++) ph[h] = 0.f;
    #pragma unroll
    for (int k = 0; k < 8; k++) {
        int i = lane + 32 * k;
        float e = xls[i] + xrt[i];
        float lr = e > 0.f ? e : 0.2f * e;
        ph[k >> 1] += lr * att[i];
    }
    #pragma unroll
    for (int h = 0; h < NHH; h++) {
        #pragma unroll
        for (int off = 16; off; off >>= 1)
            ph[h] += __shfl_xor_sync(0xffffffffu, ph[h], off);
    }
    if (lane == 0) {
        #pragma unroll
        for (int h = 0; h < NHH; h++) {
            g_logit[(size_t)widx * NHH + h] = ph[h];
            int iv = __float_as_int(ph[h]);
            iv = iv >= 0 ? iv : (iv ^ 0x7FFFFFFF);
            atomicMax(&g_mx[t * NHH + h], iv);
        }
    }
}

// ------------------------- K4: exp + segment sum -----------------------------
__global__ void k_exp(const int* __restrict__ dst)
{
    int e = blockIdx.x * blockDim.x + threadIdx.x;
    if (e >= ETOT) return;
    int t = e < EE ? dst[e] : e - EE;
    #pragma unroll
    for (int h = 0; h < NHH; h++) {
        int iv = g_mx[t * NHH + h];
        float mx = __int_as_float(iv >= 0 ? iv : (iv ^ 0x7FFFFFFF));
        float ex = expf(g_logit[(size_t)e * NHH + h] - mx);
        g_logit[(size_t)e * NHH + h] = ex;
        atomicAdd(&g_denom[t * NHH + h], ex);
    }
}

// ------------------------- K5: weighted aggregation --------------------------
// one warp per edge; head-mean folded into alpha
__global__ void k_agg(const int* __restrict__ src, const int* __restrict__ dst)
{
    int widx = (blockIdx.x * blockDim.x + threadIdx.x) >> 5;
    int lane = threadIdx.x & 31;
    if (widx >= ETOT) return;
    int s, t;
    if (widx < EE) { s = src[widx]; t = dst[widx]; }
    else           { s = t = widx - EE; }
    float alpha[NHH];
    #pragma unroll
    for (int h = 0; h < NHH; h++)
        alpha[h] = g_logit[(size_t)widx * NHH + h]
                 / (g_denom[t * NHH + h] + 1e-16f) * (1.0f / NHH);
    const float* xls = g_xl + (size_t)s * FF;
    #pragma unroll
    for (int r = 0; r < 2; r++) {
        int d = lane + 32 * r;
        float acc = 0.f;
        #pragma unroll
        for (int h = 0; h < NHH; h++) acc += alpha[h] * xls[h * DD + d];
        atomicAdd(&g_agg[t * DD + d], acc);
    }
}

// ------------------------- K6: bias + gelu -----------------------------------
__global__ void k_final(const float* __restrict__ bias, int dsel)
{
    int i = blockIdx.x * blockDim.x + threadIdx.x;
    if (i >= NN * DD) return;
    float v = g_agg[i] + bias[i & (DD - 1)];
    g_x[dsel][i] = gelu_exact(v);
}

// ------------------------- K7: interpretable fusion + heads ------------------
// one block (64 threads) per node
__global__ void k_head(int xsel, const float* __restrict__ z,
                       const float* __restrict__ qw, const float* __restrict__ qb,
                       const float* __restrict__ kw, const float* __restrict__ kb,
                       const float* __restrict__ rw1, const float* __restrict__ rb1,
                       const float* __restrict__ rw2, const float* __restrict__ rb2,
                       const float* __restrict__ uw1, const float* __restrict__ ub1,
                       const float* __restrict__ uw2, const float* __restrict__ ub2,
                       float* __restrict__ risk, float* __restrict__ unc,
                       float* __restrict__ attn)
{
    int n = blockIdx.x;
    int tid = threadIdx.x;           // 0..63
    __shared__ float xs[DD], zs[MM * DD], qs[DD], red[MM * DD], at[MM], fu[DD], hs[DD];
    xs[tid] = g_x[xsel][n * DD + tid];
    #pragma unroll
    for (int m = 0; m < MM; m++)
        zs[m * DD + tid] = z[(size_t)n * MM * DD + m * DD + tid];
    __syncthreads();
    // query
    {
        float acc = qb[tid];
        const float* w = qw + tid * DD;
        #pragma unroll
        for (int k = 0; k < DD; k++) acc += xs[k] * w[k];
        qs[tid] = acc;
    }
    __syncthreads();
    // keys: thread e computes q[e]*key[m][e] partials
    #pragma unroll
    for (int m = 0; m < MM; m++) {
        const float* w = kw + ((size_t)(m * DD + tid)) * DD;
        float acc = kb[m * DD + tid];
        #pragma unroll
        for (int k = 0; k < DD; k++) acc += zs[m * DD + k] * w[k];
        red[m * DD + tid] = acc * qs[tid];
    }
    __syncthreads();
    if (tid < MM) {
        float s = 0.f;
        for (int k = 0; k < DD; k++) s += red[tid * DD + k];
        at[tid] = s * 0.125f;   // / sqrt(64)
    }
    __syncthreads();
    if (tid == 0) {
        float mx = at[0];
        #pragma unroll
        for (int m = 1; m < MM; m++) mx = fmaxf(mx, at[m]);
        float sum = 0.f;
        #pragma unroll
        for (int m = 0; m < MM; m++) { at[m] = expf(at[m] - mx); sum += at[m]; }
        #pragma unroll
        for (int m = 0; m < MM; m++) { at[m] /= sum; attn[n * MM + m] = at[m]; }
    }
    __syncthreads();
    {
        float acc = 0.f;
        #pragma unroll
        for (int m = 0; m < MM; m++) acc += at[m] * zs[m * DD + tid];
        fu[tid] = acc;
    }
    __syncthreads();
    if (tid < 32) {
        float acc = rb1[tid];
        const float* w = rw1 + tid * DD;
        #pragma unroll
        for (int k = 0; k < DD; k++) acc += fu[k] * w[k];
        hs[tid] = gelu_exact(acc);
    } else {
        int j = tid - 32;
        float acc = ub1[j];
        const float* w = uw1 + j * DD;
        #pragma unroll
        for (int k = 0; k < DD; k++) acc += fu[k] * w[k];
        hs[tid] = gelu_exact(acc);
    }
    __syncthreads();
    if (tid == 0) {
        float acc = rb2[0];
        #pragma unroll
        for (int j = 0; j < 32; j++) acc += hs[j] * rw2[j];
        risk[n] = acc;
    } else if (tid == 1) {
        float acc = ub2[0];
        #pragma unroll
        for (int j = 0; j < 32; j++) acc += hs[32 + j] * uw2[j];
        unc[n] = 1.f / (1.f + expf(-acc));
    }
}

// ------------------------- launch --------------------------------------------
extern "C" void kernel_launch(void* const* d_in, const int* in_sizes, int n_in,
                              void* d_out, int out_size)
{
    const float* xmm  = (const float*)d_in[0];
    const int*   ei   = (const int*)  d_in[1];   // [2, E] int32 (jax x64 disabled)
    const float* ew1  = (const float*)d_in[2];
    const float* eb1  = (const float*)d_in[3];
    const float* ew2  = (const float*)d_in[4];
    const float* eb2  = (const float*)d_in[5];
    const float* fw   = (const float*)d_in[6];
    const float* fb   = (const float*)d_in[7];
    const float* gwl  = (const float*)d_in[8];
    const float* gbl  = (const float*)d_in[9];
    const float* gwr  = (const float*)d_in[10];
    const float* gbr  = (const float*)d_in[11];
    const float* gatt = (const float*)d_in[12];
    const float* gbia = (const float*)d_in[13];
    const float* qw   = (const float*)d_in[14];
    const float* qb   = (const float*)d_in[15];
    const float* kw   = (const float*)d_in[16];
    const float* kb   = (const float*)d_in[17];
    const float* rw1  = (const float*)d_in[18];
    const float* rb1  = (const float*)d_in[19];
    const float* rw2  = (const float*)d_in[20];
    const float* rb2  = (const float*)d_in[21];
    const float* uw1  = (const float*)d_in[22];
    const float* ub1  = (const float*)d_in[23];
    const float* uw2  = (const float*)d_in[24];
    const float* ub2  = (const float*)d_in[25];

    float* out    = (float*)d_out;
    float* o_risk = out;
    float* o_unc  = out + NN;
    float* o_attn = out + 2 * NN;
    float* o_z    = out + 2 * NN + NN * MM;

    const int* src = ei;
    const int* dst = ei + EE;

    k_encode<<<NN, 64>>>(xmm, ew1, eb1, ew2, eb2, fw, fb, o_z);

    int cur = 0;
    for (int l = 0; l < NLL; l++) {
        k_init<<<(NN * DD + 255) / 256, 256>>>();
        k_lin<<<NN / 8, 256>>>(cur, gwl + (size_t)l * FF * DD, gbl + l * FF,
                               gwr + (size_t)l * FF * DD, gbr + l * FF);
        k_logit<<<(ETOT + 7) / 8, 256>>>(src, dst, gatt + l * NHH * DD);
        k_exp<<<(ETOT + 127) / 128, 128>>>(dst);
        k_agg<<<(ETOT + 7) / 8, 256>>>(src, dst);
        k_final<<<(NN * DD + 255) / 256, 256>>>(gbia + l * DD, cur ^ 1);
        cur ^= 1;
    }

    k_head<<<NN, 64>>>(cur, o_z, qw, qb, kw, kb,
                       rw1, rb1, rw2, rb2, uw1, ub1, uw2, ub2,
                       o_risk, o_unc, o_attn);
}

// round 3
// speedup vs baseline: 4.1713x; 4.1713x over previous
#include <cuda_runtime.h>
#include <math.h>
#include <limits.h>

#define NN  20000
#define MM  4
#define DD  64
#define NHH 4
#define NLL 2
#define EE  320000
#define ETOT (EE + NN)
#define FF  (NHH * DD)   // 256

// ------------------------- scratch (static device globals) -------------------
__device__ float g_x[2][NN * DD];        // ping-pong node features
__device__ float g_xl[NN * FF];          // source transform
__device__ float g_xr[NN * FF];          // target transform
__device__ float g_logit[(size_t)ETOT * NHH];  // logits -> exp values
__device__ int   g_mx[NN * NHH];         // segment max (ordered-int encoding)
__device__ float g_denom[NN * NHH];      // segment sum of exp
__device__ float g_agg[NN * DD];         // aggregated output (head-mean folded)

__device__ __forceinline__ float gelu_exact(float v) {
    return 0.5f * v * (1.0f + erff(v * 0.70710678118654752f));
}

// =========================== K1: encoders + fusion ===========================
// 256 threads = 4 groups of 64; 64 nodes per block; weights staged in smem.
#define ENC_SMEM_F (576 + 8192 + 4096 + 4 * 196)
__global__ void k_encode(const float* __restrict__ xin,
                         const float* __restrict__ ew1, const float* __restrict__ eb1,
                         const float* __restrict__ ew2, const float* __restrict__ eb2,
                         const float* __restrict__ fw,  const float* __restrict__ fb,
                         float* __restrict__ z_out)
{
    extern __shared__ float sm[];
    float* s_ew1  = sm;            // 128
    float* s_eb1  = sm + 128;      // 128
    float* s_eb2  = sm + 256;      // 256
    float* s_fb   = sm + 512;      // 64
    float* s_ew2T = sm + 576;      // 8192: [m][j][d]
    float* s_fwT  = sm + 8768;     // 4096: [k][d]
    float* s_grp  = sm + 12864;    // 4 * 196

    int tid = threadIdx.x;
    int g = tid >> 6, lt = tid & 63;
    for (int i = tid; i < 128; i += 256) { s_ew1[i] = ew1[i]; s_eb1[i] = eb1[i]; }
    for (int i = tid; i < 256; i += 256) s_eb2[i] = eb2[i];
    if (tid < 64) s_fb[tid] = fb[tid];
    for (int i = tid; i < 8192; i += 256) {
        int m = i >> 11, rem = i & 2047, d = rem >> 5, j = rem & 31;
        s_ew2T[(m * 32 + j) * 64 + d] = ew2[i];
    }
    for (int i = tid; i < 4096; i += 256) {
        int d = i >> 6, k = i & 63;
        s_fwT[k * 64 + d] = fw[i];
    }
    __syncthreads();

    float* sx  = s_grp + g * 196;        // 4
    float* sh  = sx + 4;                 // 128
    float* szm = sx + 132;               // 64

    for (int it = 0; it < 16; it++) {
        int n = blockIdx.x * 64 + it * 4 + g;
        bool valid = (n < NN);
        if (valid && lt < 4) sx[lt] = xin[n * MM + lt];
        __syncthreads();
        if (valid) {
            #pragma unroll
            for (int r = 0; r < 2; r++) {
                int idx = lt + 64 * r;
                int m = idx >> 5;
                sh[idx] = gelu_exact(sx[m] * s_ew1[idx] + s_eb1[idx]);
            }
        }
        __syncthreads();
        if (valid) {
            float zm = 0.f;
            #pragma unroll
            for (int m = 0; m < MM; m++) {
                float acc = s_eb2[m * 64 + lt];
                #pragma unroll
                for (int j = 0; j < 32; j++)
                    acc += sh[m * 32 + j] * s_ew2T[(m * 32 + j) * 64 + lt];
                z_out[(size_t)n * 256 + m * 64 + lt] = acc;
                zm += acc;
            }
            szm[lt] = zm * 0.25f;
        }
        __syncthreads();
        if (valid) {
            float acc = s_fb[lt];
            #pragma unroll
            for (int k = 0; k < 64; k++) acc += szm[k] * s_fwT[k * 64 + lt];
            g_x[0][n * 64 + lt] = acc;
        }
        __syncthreads();
    }
}

// =========================== per-layer init ==================================
__global__ void k_init()
{
    int i = blockIdx.x * blockDim.x + threadIdx.x;
    if (i < NN * NHH) { g_mx[i] = INT_MIN; g_denom[i] = 0.f; }
    if (i < NN * DD)  g_agg[i] = 0.f;
}

// =========================== K2: GAT linears =================================
// 32 nodes per block, 256 threads; weights transposed into smem.
#define LIN_SMEM_F (16384 + 16384 + 2048)
__global__ void k_lin(int xsel,
                      const float* __restrict__ wl, const float* __restrict__ bl,
                      const float* __restrict__ wr, const float* __restrict__ br)
{
    extern __shared__ float sm[];
    float* swl = sm;            // [k][o] 64x256
    float* swr = sm + 16384;
    float* sx  = sm + 32768;    // 32x64
    int tid = threadIdx.x;
    int nb = blockIdx.x * 32;
    for (int i = tid; i < 16384; i += 256) {
        int o = i >> 6, k = i & 63;
        swl[k * 256 + o] = wl[i];
        swr[k * 256 + o] = wr[i];
    }
    const float* xsrc = g_x[xsel] + (size_t)nb * 64;
    for (int i = tid; i < 2048; i += 256) sx[i] = xsrc[i];
    __syncthreads();

    int o = tid;
    float blv = bl[o], brv = br[o];
    #pragma unroll
    for (int c = 0; c < 4; c++) {
        float aL[8], aR[8];
        #pragma unroll
        for (int i = 0; i < 8; i++) { aL[i] = 0.f; aR[i] = 0.f; }
        for (int k = 0; k < 64; k++) {
            float w1 = swl[k * 256 + o];
            float w2 = swr[k * 256 + o];
            #pragma unroll
            for (int i = 0; i < 8; i++) {
                float xv = sx[(c * 8 + i) * 64 + k];
                aL[i] += xv * w1;
                aR[i] += xv * w2;
            }
        }
        #pragma unroll
        for (int i = 0; i < 8; i++) {
            size_t row = (size_t)(nb + c * 8 + i) * FF;
            g_xl[row + o] = aL[i] + blv;
            g_xr[row + o] = aR[i] + brv;
        }
    }
}

// =========================== K3: edge logits + segment max ===================
// one warp per edge; float4 gathers; 8 lanes per head
__global__ void k_logit(const int* __restrict__ src, const int* __restrict__ dst,
                        const float* __restrict__ att)
{
    int widx = (blockIdx.x * blockDim.x + threadIdx.x) >> 5;
    int lane = threadIdx.x & 31;
    if (widx >= ETOT) return;
    int s, t;
    if (widx < EE) { s = src[widx]; t = dst[widx]; }
    else           { s = t = widx - EE; }
    const float4* xls = (const float4*)(g_xl + (size_t)s * FF);
    const float4* xrt = (const float4*)(g_xr + (size_t)t * FF);
    const float4* a4  = (const float4*)att;
    float sum = 0.f;
    #pragma unroll
    for (int q = 0; q < 2; q++) {
        float4 xl = xls[lane * 2 + q];
        float4 xr = xrt[lane * 2 + q];
        float4 av = a4[lane * 2 + q];
        float e;
        e = xl.x + xr.x; sum += (e > 0.f ? e : 0.2f * e) * av.x;
        e = xl.y + xr.y; sum += (e > 0.f ? e : 0.2f * e) * av.y;
        e = xl.z + xr.z; sum += (e > 0.f ? e : 0.2f * e) * av.z;
        e = xl.w + xr.w; sum += (e > 0.f ? e : 0.2f * e) * av.w;
    }
    sum += __shfl_xor_sync(0xffffffffu, sum, 1);
    sum += __shfl_xor_sync(0xffffffffu, sum, 2);
    sum += __shfl_xor_sync(0xffffffffu, sum, 4);
    if ((lane & 7) == 0) {
        int h = lane >> 3;
        g_logit[(size_t)widx * NHH + h] = sum;
        int iv = __float_as_int(sum);
        iv = iv >= 0 ? iv : (iv ^ 0x7FFFFFFF);
        atomicMax(&g_mx[t * NHH + h], iv);
    }
}

// =========================== K4: exp + segment sum ===========================
__global__ void k_exp(const int* __restrict__ dst)
{
    int e = blockIdx.x * blockDim.x + threadIdx.x;
    if (e >= ETOT) return;
    int t = e < EE ? dst[e] : e - EE;
    #pragma unroll
    for (int h = 0; h < NHH; h++) {
        int iv = g_mx[t * NHH + h];
        float mx = __int_as_float(iv >= 0 ? iv : (iv ^ 0x7FFFFFFF));
        float ex = expf(g_logit[(size_t)e * NHH + h] - mx);
        g_logit[(size_t)e * NHH + h] = ex;
        atomicAdd(&g_denom[t * NHH + h], ex);
    }
}

// =========================== K5: weighted aggregation ========================
__global__ void k_agg(const int* __restrict__ src, const int* __restrict__ dst)
{
    int widx = (blockIdx.x * blockDim.x + threadIdx.x) >> 5;
    int lane = threadIdx.x & 31;
    if (widx >= ETOT) return;
    int s, t;
    if (widx < EE) { s = src[widx]; t = dst[widx]; }
    else           { s = t = widx - EE; }
    float4 lg = *(const float4*)(g_logit + (size_t)widx * NHH);
    float4 dn = *(const float4*)(g_denom + (size_t)t * NHH);
    float alpha[NHH];
    alpha[0] = lg.x / (dn.x + 1e-16f) * (1.0f / NHH);
    alpha[1] = lg.y / (dn.y + 1e-16f) * (1.0f / NHH);
    alpha[2] = lg.z / (dn.z + 1e-16f) * (1.0f / NHH);
    alpha[3] = lg.w / (dn.w + 1e-16f) * (1.0f / NHH);
    const float* xls = g_xl + (size_t)s * FF;
    #pragma unroll
    for (int r = 0; r < 2; r++) {
        int d = lane + 32 * r;
        float acc = 0.f;
        #pragma unroll
        for (int h = 0; h < NHH; h++) acc += alpha[h] * xls[h * DD + d];
        atomicAdd(&g_agg[t * DD + d], acc);
    }
}

// =========================== K6: bias + gelu =================================
__global__ void k_final(const float* __restrict__ bias, int dsel)
{
    int i = blockIdx.x * blockDim.x + threadIdx.x;
    if (i >= NN * DD) return;
    float v = g_agg[i] + bias[i & (DD - 1)];
    g_x[dsel][i] = gelu_exact(v);
}

// =========================== K7: fusion + heads ==============================
// 256 threads = 4 groups of 64; 64 nodes per block; weights in smem.
#define HEAD_GRP_F 772
#define HEAD_SMEM_F (25028 + 4 * HEAD_GRP_F)
__global__ void k_head(int xsel, const float* __restrict__ z,
                       const float* __restrict__ qw, const float* __restrict__ qb,
                       const float* __restrict__ kw, const float* __restrict__ kb,
                       const float* __restrict__ rw1, const float* __restrict__ rb1,
                       const float* __restrict__ rw2, const float* __restrict__ rb2,
                       const float* __restrict__ uw1, const float* __restrict__ ub1,
                       const float* __restrict__ uw2, const float* __restrict__ ub2,
                       float* __restrict__ risk, float* __restrict__ unc,
                       float* __restrict__ attn)
{
    extern __shared__ float sm[];
    float* s_qwT  = sm;             // 4096  [k][d]
    float* s_kwT  = sm + 4096;      // 16384 [m][k][e]
    float* s_rw1T = sm + 20480;     // 2048  [k][j]
    float* s_uw1T = sm + 22528;     // 2048
    float* s_rw2  = sm + 24576;     // 32
    float* s_uw2  = sm + 24608;     // 32
    float* s_qb   = sm + 24640;     // 64
    float* s_kb   = sm + 24704;     // 256
    float* s_rb1  = sm + 24960;     // 32
    float* s_ub1  = sm + 24992;     // 32
    float* s_sc2  = sm + 25024;     // 2: rb2, ub2
    float* s_grp  = sm + 25028;

    int tid = threadIdx.x;
    int g = tid >> 6, lt = tid & 63;

    for (int i = tid; i < 4096; i += 256) {
        int d = i >> 6, k = i & 63;
        s_qwT[k * 64 + d] = qw[i];
    }
    for (int i = tid; i < 16384; i += 256) {
        int m = i >> 12, rem = i & 4095, e = rem >> 6, k = rem & 63;
        s_kwT[(m * 64 + k) * 64 + e] = kw[i];
    }
    for (int i = tid; i < 2048; i += 256) {
        int j = i >> 6, k = i & 63;
        s_rw1T[k * 32 + j] = rw1[i];
        s_uw1T[k * 32 + j] = uw1[i];
    }
    if (tid < 32) { s_rw2[tid] = rw2[tid]; s_uw2[tid] = uw2[tid]; }
    if (tid < 64) s_qb[tid] = qb[tid];
    for (int i = tid; i < 256; i += 256) s_kb[i] = kb[i];
    if (tid < 32) { s_rb1[tid] = rb1[tid]; s_ub1[tid] = ub1[tid]; }
    if (tid == 0) { s_sc2[0] = rb2[0]; s_sc2[1] = ub2[0]; }
    __syncthreads();

    float* xs  = s_grp + g * HEAD_GRP_F;  // 64
    float* zs  = xs + 64;                 // 256
    float* red = xs + 320;                // 256
    float* at  = xs + 576;                // 4
    float* fu  = xs + 580;                // 64
    float* hs  = xs + 644;                // 64

    for (int it = 0; it < 16; it++) {
        int n = blockIdx.x * 64 + it * 4 + g;
        bool valid = (n < NN);
        float qv = 0.f;
        if (valid) {
            xs[lt] = g_x[xsel][n * 64 + lt];
            #pragma unroll
            for (int m = 0; m < MM; m++)
                zs[m * 64 + lt] = z[(size_t)n * 256 + m * 64 + lt];
        }
        __syncthreads();
        if (valid) {
            float acc = s_qb[lt];
            #pragma unroll
            for (int k = 0; k < 64; k++) acc += xs[k] * s_qwT[k * 64 + lt];
            qv = acc;
            #pragma unroll
            for (int m = 0; m < MM; m++) {
                float a2 = s_kb[m * 64 + lt];
                #pragma unroll
                for (int k = 0; k < 64; k++)
                    a2 += zs[m * 64 + k] * s_kwT[(m * 64 + k) * 64 + lt];
                red[m * 64 + lt] = a2 * qv;
            }
        }
        __syncthreads();
        if (valid && lt < MM) {
            float s = 0.f;
            #pragma unroll
            for (int k = 0; k < 64; k++) s += red[lt * 64 + k];
            at[lt] = s * 0.125f;
        }
        __syncthreads();
        if (valid && lt == 0) {
            float mx = fmaxf(fmaxf(at[0], at[1]), fmaxf(at[2], at[3]));
            float sum = 0.f;
            #pragma unroll
            for (int m = 0; m < MM; m++) { at[m] = expf(at[m] - mx); sum += at[m]; }
            float inv = 1.f / sum;
            #pragma unroll
            for (int m = 0; m < MM; m++) { at[m] *= inv; attn[n * MM + m] = at[m]; }
        }
        __syncthreads();
        if (valid) {
            float acc = 0.f;
            #pragma unroll
            for (int m = 0; m < MM; m++) acc += at[m] * zs[m * 64 + lt];
            fu[lt] = acc;
        }
        __syncthreads();
        if (valid) {
            if (lt < 32) {
                float acc = s_rb1[lt];
                #pragma unroll
                for (int k = 0; k < 64; k++) acc += fu[k] * s_rw1T[k * 32 + lt];
                hs[lt] = gelu_exact(acc);
            } else {
                int j = lt - 32;
                float acc = s_ub1[j];
                #pragma unroll
                for (int k = 0; k < 64; k++) acc += fu[k] * s_uw1T[k * 32 + j];
                hs[lt] = gelu_exact(acc);
            }
        }
        __syncthreads();
        if (valid && lt == 0) {
            float acc = s_sc2[0];
            #pragma unroll
            for (int j = 0; j < 32; j++) acc += hs[j] * s_rw2[j];
            risk[n] = acc;
        }
        if (valid && lt == 1) {
            float acc = s_sc2[1];
            #pragma unroll
            for (int j = 0; j < 32; j++) acc += hs[32 + j] * s_uw2[j];
            unc[n] = 1.f / (1.f + expf(-acc));
        }
        __syncthreads();
    }
}

// =========================== launch ==========================================
extern "C" void kernel_launch(void* const* d_in, const int* in_sizes, int n_in,
                              void* d_out, int out_size)
{
    const float* xmm  = (const float*)d_in[0];
    const int*   ei   = (const int*)  d_in[1];
    const float* ew1  = (const float*)d_in[2];
    const float* eb1  = (const float*)d_in[3];
    const float* ew2  = (const float*)d_in[4];
    const float* eb2  = (const float*)d_in[5];
    const float* fw   = (const float*)d_in[6];
    const float* fb   = (const float*)d_in[7];
    const float* gwl  = (const float*)d_in[8];
    const float* gbl  = (const float*)d_in[9];
    const float* gwr  = (const float*)d_in[10];
    const float* gbr  = (const float*)d_in[11];
    const float* gatt = (const float*)d_in[12];
    const float* gbia = (const float*)d_in[13];
    const float* qw   = (const float*)d_in[14];
    const float* qb   = (const float*)d_in[15];
    const float* kw   = (const float*)d_in[16];
    const float* kb   = (const float*)d_in[17];
    const float* rw1  = (const float*)d_in[18];
    const float* rb1  = (const float*)d_in[19];
    const float* rw2  = (const float*)d_in[20];
    const float* rb2  = (const float*)d_in[21];
    const float* uw1  = (const float*)d_in[22];
    const float* ub1  = (const float*)d_in[23];
    const float* uw2  = (const float*)d_in[24];
    const float* ub2  = (const float*)d_in[25];

    float* out    = (float*)d_out;
    float* o_risk = out;
    float* o_unc  = out + NN;
    float* o_attn = out + 2 * NN;
    float* o_z    = out + 2 * NN + NN * MM;

    const int* src = ei;
    const int* dst = ei + EE;

    // idempotent, called every invocation (no static guards per harness rules)
    cudaFuncSetAttribute(k_encode, cudaFuncAttributeMaxDynamicSharedMemorySize,
                         ENC_SMEM_F * 4);
    cudaFuncSetAttribute(k_lin, cudaFuncAttributeMaxDynamicSharedMemorySize,
                         LIN_SMEM_F * 4);
    cudaFuncSetAttribute(k_head, cudaFuncAttributeMaxDynamicSharedMemorySize,
                         HEAD_SMEM_F * 4);

    k_encode<<<(NN + 63) / 64, 256, ENC_SMEM_F * 4>>>(xmm, ew1, eb1, ew2, eb2,
                                                      fw, fb, o_z);

    int cur = 0;
    for (int l = 0; l < NLL; l++) {
        k_init<<<(NN * DD + 255) / 256, 256>>>();
        k_lin<<<NN / 32, 256, LIN_SMEM_F * 4>>>(cur,
                               gwl + (size_t)l * FF * DD, gbl + l * FF,
                               gwr + (size_t)l * FF * DD, gbr + l * FF);
        k_logit<<<(ETOT + 7) / 8, 256>>>(src, dst, gatt + l * NHH * DD);
        k_exp<<<(ETOT + 127) / 128, 128>>>(dst);
        k_agg<<<(ETOT + 7) / 8, 256>>>(src, dst);
        k_final<<<(NN * DD + 255) / 256, 256>>>(gbia + l * DD, cur ^ 1);
        cur ^= 1;
    }

    k_head<<<(NN + 63) / 64, 256, HEAD_SMEM_F * 4>>>(cur, o_z, qw, qb, kw, kb,
                       rw1, rb1, rw2, rb2, uw1, ub1, uw2, ub2,
                       o_risk, o_unc, o_attn);
}

// round 4
// speedup vs baseline: 5.4143x; 1.2980x over previous
#include <cuda_runtime.h>
#include <math.h>
#include <float.h>
#include <limits.h>

#define NN  20000
#define MM  4
#define DD  64
#define NHH 4
#define NLL 2
#define EE  320000
#define ETOT (EE + NN)
#define FF  (NHH * DD)   // 256

// ------------------------- scratch (static device globals) -------------------
__device__ float g_x[2][NN * DD];        // ping-pong node features
__device__ float g_xl[NN * FF];          // source transform
__device__ float g_xr[NN * FF];          // target transform
__device__ int   g_cnt[NN];              // in-degree counts
__device__ int   g_ptr[NN + 1];          // CSR row pointers (by dst)
__device__ int   g_ofs[NN];              // running offsets for scatter
__device__ int   g_csrc[ETOT];           // src node per CSR slot

__device__ __forceinline__ float gelu_exact(float v) {
    return 0.5f * v * (1.0f + erff(v * 0.70710678118654752f));
}

// =========================== CSR build =======================================
__global__ void k_zero()
{
    int i = blockIdx.x * blockDim.x + threadIdx.x;
    if (i < NN) g_cnt[i] = 0;
}

__global__ void k_count(const int* __restrict__ dst)
{
    int e = blockIdx.x * blockDim.x + threadIdx.x;
    if (e >= ETOT) return;
    int t = e < EE ? dst[e] : e - EE;
    atomicAdd(&g_cnt[t], 1);
}

// single block, 1024 threads; chunk of 20 nodes per thread
__global__ void k_scan()
{
    __shared__ int s[1024];
    int t = threadIdx.x;
    int base = t * 20;
    int partial = 0;
    #pragma unroll
    for (int j = 0; j < 20; j++) {
        int idx = base + j;
        if (idx < NN) partial += g_cnt[idx];
    }
    s[t] = partial;
    __syncthreads();
    for (int off = 1; off < 1024; off <<= 1) {
        int v = (t >= off) ? s[t - off] : 0;
        __syncthreads();
        s[t] += v;
        __syncthreads();
    }
    int run = s[t] - partial;     // exclusive base for this chunk
    #pragma unroll
    for (int j = 0; j < 20; j++) {
        int idx = base + j;
        if (idx < NN) {
            g_ptr[idx] = run;
            g_ofs[idx] = run;
            run += g_cnt[idx];
        }
    }
    if (t == 0) g_ptr[NN] = ETOT;
}

__global__ void k_scatter(const int* __restrict__ src, const int* __restrict__ dst)
{
    int e = blockIdx.x * blockDim.x + threadIdx.x;
    if (e >= ETOT) return;
    int s, t;
    if (e < EE) { s = src[e]; t = dst[e]; }
    else        { s = t = e - EE; }
    int pos = atomicAdd(&g_ofs[t], 1);
    g_csrc[pos] = s;
}

// =========================== K1: encoders + fusion ===========================
#define ENC_SMEM_F (576 + 8192 + 4096 + 4 * 196)
__global__ void k_encode(const float* __restrict__ xin,
                         const float* __restrict__ ew1, const float* __restrict__ eb1,
                         const float* __restrict__ ew2, const float* __restrict__ eb2,
                         const float* __restrict__ fw,  const float* __restrict__ fb,
                         float* __restrict__ z_out)
{
    extern __shared__ float sm[];
    float* s_ew1  = sm;            // 128
    float* s_eb1  = sm + 128;      // 128
    float* s_eb2  = sm + 256;      // 256
    float* s_fb   = sm + 512;      // 64
    float* s_ew2T = sm + 576;      // 8192: [m][j][d]
    float* s_fwT  = sm + 8768;     // 4096: [k][d]
    float* s_grp  = sm + 12864;    // 4 * 196

    int tid = threadIdx.x;
    int g = tid >> 6, lt = tid & 63;
    for (int i = tid; i < 128; i += 256) { s_ew1[i] = ew1[i]; s_eb1[i] = eb1[i]; }
    for (int i = tid; i < 256; i += 256) s_eb2[i] = eb2[i];
    if (tid < 64) s_fb[tid] = fb[tid];
    for (int i = tid; i < 8192; i += 256) {
        int m = i >> 11, rem = i & 2047, d = rem >> 5, j = rem & 31;
        s_ew2T[(m * 32 + j) * 64 + d] = ew2[i];
    }
    for (int i = tid; i < 4096; i += 256) {
        int d = i >> 6, k = i & 63;
        s_fwT[k * 64 + d] = fw[i];
    }
    __syncthreads();

    float* sx  = s_grp + g * 196;
    float* sh  = sx + 4;
    float* szm = sx + 132;

    for (int it = 0; it < 16; it++) {
        int n = blockIdx.x * 64 + it * 4 + g;
        bool valid = (n < NN);
        if (valid && lt < 4) sx[lt] = xin[n * MM + lt];
        __syncthreads();
        if (valid) {
            #pragma unroll
            for (int r = 0; r < 2; r++) {
                int idx = lt + 64 * r;
                int m = idx >> 5;
                sh[idx] = gelu_exact(sx[m] * s_ew1[idx] + s_eb1[idx]);
            }
        }
        __syncthreads();
        if (valid) {
            float zm = 0.f;
            #pragma unroll
            for (int m = 0; m < MM; m++) {
                float acc = s_eb2[m * 64 + lt];
                #pragma unroll
                for (int j = 0; j < 32; j++)
                    acc += sh[m * 32 + j] * s_ew2T[(m * 32 + j) * 64 + lt];
                z_out[(size_t)n * 256 + m * 64 + lt] = acc;
                zm += acc;
            }
            szm[lt] = zm * 0.25f;
        }
        __syncthreads();
        if (valid) {
            float acc = s_fb[lt];
            #pragma unroll
            for (int k = 0; k < 64; k++) acc += szm[k] * s_fwT[k * 64 + lt];
            g_x[0][n * 64 + lt] = acc;
        }
        __syncthreads();
    }
}

// =========================== K2: GAT linears (64 nodes/block) ================
#define LIN_SMEM_F (16384 + 16384 + 4096)
__global__ void k_lin(int xsel,
                      const float* __restrict__ wl, const float* __restrict__ bl,
                      const float* __restrict__ wr, const float* __restrict__ br)
{
    extern __shared__ float sm[];
    float* swl = sm;            // [k][o] 64x256
    float* swr = sm + 16384;
    float* sx  = sm + 32768;    // 64x64
    int tid = threadIdx.x;
    int nb = blockIdx.x * 64;
    for (int i = tid; i < 16384; i += 256) {
        int o = i >> 6, k = i & 63;
        swl[k * 256 + o] = wl[i];
        swr[k * 256 + o] = wr[i];
    }
    const float* xsrc = g_x[xsel] + (size_t)nb * 64;
    for (int i = tid; i < 4096; i += 256) sx[i] = xsrc[i];
    __syncthreads();

    int o = tid;
    float blv = bl[o], brv = br[o];
    #pragma unroll
    for (int c = 0; c < 8; c++) {
        float aL[8], aR[8];
        #pragma unroll
        for (int i = 0; i < 8; i++) { aL[i] = 0.f; aR[i] = 0.f; }
        for (int k = 0; k < 64; k++) {
            float w1 = swl[k * 256 + o];
            float w2 = swr[k * 256 + o];
            #pragma unroll
            for (int i = 0; i < 8; i++) {
                float xv = sx[(c * 8 + i) * 64 + k];
                aL[i] += xv * w1;
                aR[i] += xv * w2;
            }
        }
        #pragma unroll
        for (int i = 0; i < 8; i++) {
            size_t row = (size_t)(nb + c * 8 + i) * FF;
            g_xl[row + o] = aL[i] + blv;
            g_xr[row + o] = aR[i] + brv;
        }
    }
}

// =========================== K3: fused GAT edge phase ========================
// one warp per destination node; online softmax; all state in registers.
// lane layout: col = lane*8 + q (q=0..7); head = lane>>3 (8 lanes per head).
__global__ void k_gat(const float* __restrict__ att, const float* __restrict__ bias,
                      int xsel, int dsel)
{
    int node = blockIdx.x * 8 + (threadIdx.x >> 5);
    if (node >= NN) return;
    int lane = threadIdx.x & 31;

    const float4* xr4 = (const float4*)(g_xr + (size_t)node * FF);
    float4 xr0 = xr4[lane * 2];
    float4 xr1 = xr4[lane * 2 + 1];
    const float4* a4 = (const float4*)att;
    float4 av0 = a4[lane * 2];
    float4 av1 = a4[lane * 2 + 1];

    float m = -FLT_MAX, den = 0.f;
    float acc0x = 0.f, acc0y = 0.f, acc0z = 0.f, acc0w = 0.f;
    float acc1x = 0.f, acc1y = 0.f, acc1z = 0.f, acc1w = 0.f;

    int beg = g_ptr[node], end = g_ptr[node + 1];
    for (int i = beg; i < end; i++) {
        int s = g_csrc[i];
        const float4* xl4 = (const float4*)(g_xl + (size_t)s * FF);
        float4 l0 = xl4[lane * 2];
        float4 l1 = xl4[lane * 2 + 1];
        float p = 0.f, e;
        e = l0.x + xr0.x; p += (e > 0.f ? e : 0.2f * e) * av0.x;
        e = l0.y + xr0.y; p += (e > 0.f ? e : 0.2f * e) * av0.y;
        e = l0.z + xr0.z; p += (e > 0.f ? e : 0.2f * e) * av0.z;
        e = l0.w + xr0.w; p += (e > 0.f ? e : 0.2f * e) * av0.w;
        e = l1.x + xr1.x; p += (e > 0.f ? e : 0.2f * e) * av1.x;
        e = l1.y + xr1.y; p += (e > 0.f ? e : 0.2f * e) * av1.y;
        e = l1.z + xr1.z; p += (e > 0.f ? e : 0.2f * e) * av1.z;
        e = l1.w + xr1.w; p += (e > 0.f ? e : 0.2f * e) * av1.w;
        // allreduce within 8-lane head group
        p += __shfl_xor_sync(0xffffffffu, p, 1);
        p += __shfl_xor_sync(0xffffffffu, p, 2);
        p += __shfl_xor_sync(0xffffffffu, p, 4);
        // online softmax update
        float mn = fmaxf(m, p);
        float cr = __expf(m - mn);
        float pe = __expf(p - mn);
        den = den * cr + pe;
        acc0x = acc0x * cr + pe * l0.x;
        acc0y = acc0y * cr + pe * l0.y;
        acc0z = acc0z * cr + pe * l0.z;
        acc0w = acc0w * cr + pe * l0.w;
        acc1x = acc1x * cr + pe * l1.x;
        acc1y = acc1y * cr + pe * l1.y;
        acc1z = acc1z * cr + pe * l1.z;
        acc1w = acc1w * cr + pe * l1.w;
        m = mn;
    }

    float inv = 1.f / (den + 1e-16f);
    float v[8];
    v[0] = acc0x * inv; v[1] = acc0y * inv; v[2] = acc0z * inv; v[3] = acc0w * inv;
    v[4] = acc1x * inv; v[5] = acc1y * inv; v[6] = acc1z * inv; v[7] = acc1w * inv;
    // sum across heads (lanes differing in bits 3,4)
    #pragma unroll
    for (int q = 0; q < 8; q++) {
        v[q] += __shfl_xor_sync(0xffffffffu, v[q], 8);
        v[q] += __shfl_xor_sync(0xffffffffu, v[q], 16);
    }
    if (lane < 8) {
        float o[8];
        const float* bs = bias + lane * 8;
        #pragma unroll
        for (int q = 0; q < 8; q++)
            o[q] = gelu_exact(0.25f * v[q] + bs[q]);
        float4* dst4 = (float4*)(g_x[dsel] + (size_t)node * DD + lane * 8);
        dst4[0] = make_float4(o[0], o[1], o[2], o[3]);
        dst4[1] = make_float4(o[4], o[5], o[6], o[7]);
    }
}

// =========================== K7: fusion + heads ==============================
#define HEAD_GRP_F 772
#define HEAD_SMEM_F (25028 + 4 * HEAD_GRP_F)
__global__ void k_head(int xsel, const float* __restrict__ z,
                       const float* __restrict__ qw, const float* __restrict__ qb,
                       const float* __restrict__ kw, const float* __restrict__ kb,
                       const float* __restrict__ rw1, const float* __restrict__ rb1,
                       const float* __restrict__ rw2, const float* __restrict__ rb2,
                       const float* __restrict__ uw1, const float* __restrict__ ub1,
                       const float* __restrict__ uw2, const float* __restrict__ ub2,
                       float* __restrict__ risk, float* __restrict__ unc,
                       float* __restrict__ attn)
{
    extern __shared__ float sm[];
    float* s_qwT  = sm;             // 4096  [k][d]
    float* s_kwT  = sm + 4096;      // 16384 [m][k][e]
    float* s_rw1T = sm + 20480;     // 2048  [k][j]
    float* s_uw1T = sm + 22528;     // 2048
    float* s_rw2  = sm + 24576;     // 32
    float* s_uw2  = sm + 24608;     // 32
    float* s_qb   = sm + 24640;     // 64
    float* s_kb   = sm + 24704;     // 256
    float* s_rb1  = sm + 24960;     // 32
    float* s_ub1  = sm + 24992;     // 32
    float* s_sc2  = sm + 25024;     // 2
    float* s_grp  = sm + 25028;

    int tid = threadIdx.x;
    int g = tid >> 6, lt = tid & 63;

    for (int i = tid; i < 4096; i += 256) {
        int d = i >> 6, k = i & 63;
        s_qwT[k * 64 + d] = qw[i];
    }
    for (int i = tid; i < 16384; i += 256) {
        int m = i >> 12, rem = i & 4095, e = rem >> 6, k = rem & 63;
        s_kwT[(m * 64 + k) * 64 + e] = kw[i];
    }
    for (int i = tid; i < 2048; i += 256) {
        int j = i >> 6, k = i & 63;
        s_rw1T[k * 32 + j] = rw1[i];
        s_uw1T[k * 32 + j] = uw1[i];
    }
    if (tid < 32) { s_rw2[tid] = rw2[tid]; s_uw2[tid] = uw2[tid]; }
    if (tid < 64) s_qb[tid] = qb[tid];
    for (int i = tid; i < 256; i += 256) s_kb[i] = kb[i];
    if (tid < 32) { s_rb1[tid] = rb1[tid]; s_ub1[tid] = ub1[tid]; }
    if (tid == 0) { s_sc2[0] = rb2[0]; s_sc2[1] = ub2[0]; }
    __syncthreads();

    float* xs  = s_grp + g * HEAD_GRP_F;
    float* zs  = xs + 64;
    float* red = xs + 320;
    float* at  = xs + 576;
    float* fu  = xs + 580;
    float* hs  = xs + 644;

    for (int it = 0; it < 16; it++) {
        int n = blockIdx.x * 64 + it * 4 + g;
        bool valid = (n < NN);
        if (valid) {
            xs[lt] = g_x[xsel][n * 64 + lt];
            #pragma unroll
            for (int m = 0; m < MM; m++)
                zs[m * 64 + lt] = z[(size_t)n * 256 + m * 64 + lt];
        }
        __syncthreads();
        if (valid) {
            float acc = s_qb[lt];
            #pragma unroll
            for (int k = 0; k < 64; k++) acc += xs[k] * s_qwT[k * 64 + lt];
            float qv = acc;
            #pragma unroll
            for (int m = 0; m < MM; m++) {
                float a2 = s_kb[m * 64 + lt];
                #pragma unroll
                for (int k = 0; k < 64; k++)
                    a2 += zs[m * 64 + k] * s_kwT[(m * 64 + k) * 64 + lt];
                red[m * 64 + lt] = a2 * qv;
            }
        }
        __syncthreads();
        if (valid && lt < MM) {
            float s = 0.f;
            #pragma unroll
            for (int k = 0; k < 64; k++) s += red[lt * 64 + k];
            at[lt] = s * 0.125f;
        }
        __syncthreads();
        if (valid && lt == 0) {
            float mx = fmaxf(fmaxf(at[0], at[1]), fmaxf(at[2], at[3]));
            float sum = 0.f;
            #pragma unroll
            for (int m = 0; m < MM; m++) { at[m] = expf(at[m] - mx); sum += at[m]; }
            float iv = 1.f / sum;
            #pragma unroll
            for (int m = 0; m < MM; m++) { at[m] *= iv; attn[n * MM + m] = at[m]; }
        }
        __syncthreads();
        if (valid) {
            float acc = 0.f;
            #pragma unroll
            for (int m = 0; m < MM; m++) acc += at[m] * zs[m * 64 + lt];
            fu[lt] = acc;
        }
        __syncthreads();
        if (valid) {
            if (lt < 32) {
                float acc = s_rb1[lt];
                #pragma unroll
                for (int k = 0; k < 64; k++) acc += fu[k] * s_rw1T[k * 32 + lt];
                hs[lt] = gelu_exact(acc);
            } else {
                int j = lt - 32;
                float acc = s_ub1[j];
                #pragma unroll
                for (int k = 0; k < 64; k++) acc += fu[k] * s_uw1T[k * 32 + j];
                hs[lt] = gelu_exact(acc);
            }
        }
        __syncthreads();
        if (valid && lt == 0) {
            float acc = s_sc2[0];
            #pragma unroll
            for (int j = 0; j < 32; j++) acc += hs[j] * s_rw2[j];
            risk[n] = acc;
        }
        if (valid && lt == 1) {
            float acc = s_sc2[1];
            #pragma unroll
            for (int j = 0; j < 32; j++) acc += hs[32 + j] * s_uw2[j];
            unc[n] = 1.f / (1.f + expf(-acc));
        }
        __syncthreads();
    }
}

// =========================== launch ==========================================
extern "C" void kernel_launch(void* const* d_in, const int* in_sizes, int n_in,
                              void* d_out, int out_size)
{
    const float* xmm  = (const float*)d_in[0];
    const int*   ei   = (const int*)  d_in[1];
    const float* ew1  = (const float*)d_in[2];
    const float* eb1  = (const float*)d_in[3];
    const float* ew2  = (const float*)d_in[4];
    const float* eb2  = (const float*)d_in[5];
    const float* fw   = (const float*)d_in[6];
    const float* fb   = (const float*)d_in[7];
    const float* gwl  = (const float*)d_in[8];
    const float* gbl  = (const float*)d_in[9];
    const float* gwr  = (const float*)d_in[10];
    const float* gbr  = (const float*)d_in[11];
    const float* gatt = (const float*)d_in[12];
    const float* gbia = (const float*)d_in[13];
    const float* qw   = (const float*)d_in[14];
    const float* qb   = (const float*)d_in[15];
    const float* kw   = (const float*)d_in[16];
    const float* kb   = (const float*)d_in[17];
    const float* rw1  = (const float*)d_in[18];
    const float* rb1  = (const float*)d_in[19];
    const float* rw2  = (const float*)d_in[20];
    const float* rb2  = (const float*)d_in[21];
    const float* uw1  = (const float*)d_in[22];
    const float* ub1  = (const float*)d_in[23];
    const float* uw2  = (const float*)d_in[24];
    const float* ub2  = (const float*)d_in[25];

    float* out    = (float*)d_out;
    float* o_risk = out;
    float* o_unc  = out + NN;
    float* o_attn = out + 2 * NN;
    float* o_z    = out + 2 * NN + NN * MM;

    const int* src = ei;
    const int* dst = ei + EE;

    cudaFuncSetAttribute(k_encode, cudaFuncAttributeMaxDynamicSharedMemorySize,
                         ENC_SMEM_F * 4);
    cudaFuncSetAttribute(k_lin, cudaFuncAttributeMaxDynamicSharedMemorySize,
                         LIN_SMEM_F * 4);
    cudaFuncSetAttribute(k_head, cudaFuncAttributeMaxDynamicSharedMemorySize,
                         HEAD_SMEM_F * 4);

    // CSR build (edge set is layer-independent)
    k_zero<<<(NN + 255) / 256, 256>>>();
    k_count<<<(ETOT + 255) / 256, 256>>>(dst);
    k_scan<<<1, 1024>>>();
    k_scatter<<<(ETOT + 255) / 256, 256>>>(src, dst);

    k_encode<<<(NN + 63) / 64, 256, ENC_SMEM_F * 4>>>(xmm, ew1, eb1, ew2, eb2,
                                                      fw, fb, o_z);

    int cur = 0;
    for (int l = 0; l < NLL; l++) {
        k_lin<<<(NN + 63) / 64, 256, LIN_SMEM_F * 4>>>(cur,
                               gwl + (size_t)l * FF * DD, gbl + l * FF,
                               gwr + (size_t)l * FF * DD, gbr + l * FF);
        k_gat<<<(NN + 7) / 8, 256>>>(gatt + l * NHH * DD, gbia + l * DD,
                                     cur, cur ^ 1);
        cur ^= 1;
    }

    k_head<<<(NN + 63) / 64, 256, HEAD_SMEM_F * 4>>>(cur, o_z, qw, qb, kw, kb,
                       rw1, rb1, rw2, rb2, uw1, ub1, uw2, ub2,
                       o_risk, o_unc, o_attn);
}

// round 5
// speedup vs baseline: 6.5370x; 1.2073x over previous
#include <cuda_runtime.h>
#include <math.h>
#include <float.h>
#include <limits.h>

#define NN  20000
#define MM  4
#define DD  64
#define NHH 4
#define NLL 2
#define EE  320000
#define ETOT (EE + NN)
#define FF  (NHH * DD)   // 256

// ------------------------- scratch (static device globals) -------------------
__device__ float g_x[2][NN * DD];
__device__ float g_xl[NN * FF];
__device__ float g_xr[NN * FF];
__device__ int   g_cnt[NN];
__device__ int   g_ptr[NN + 1];
__device__ int   g_ofs[NN];
__device__ int   g_csrc[ETOT];

__device__ __forceinline__ float gelu_exact(float v) {
    return 0.5f * v * (1.0f + erff(v * 0.70710678118654752f));
}

// =========================== CSR build =======================================
__global__ void k_zero()
{
    int i = blockIdx.x * blockDim.x + threadIdx.x;
    if (i < NN) g_cnt[i] = 0;
}

__global__ void k_count(const int* __restrict__ dst)
{
    int e = blockIdx.x * blockDim.x + threadIdx.x;
    if (e >= ETOT) return;
    int t = e < EE ? dst[e] : e - EE;
    atomicAdd(&g_cnt[t], 1);
}

__global__ void k_scan()
{
    __shared__ int s[1024];
    int t = threadIdx.x;
    int base = t * 20;
    int partial = 0;
    #pragma unroll
    for (int j = 0; j < 20; j++) {
        int idx = base + j;
        if (idx < NN) partial += g_cnt[idx];
    }
    s[t] = partial;
    __syncthreads();
    for (int off = 1; off < 1024; off <<= 1) {
        int v = (t >= off) ? s[t - off] : 0;
        __syncthreads();
        s[t] += v;
        __syncthreads();
    }
    int run = s[t] - partial;
    #pragma unroll
    for (int j = 0; j < 20; j++) {
        int idx = base + j;
        if (idx < NN) {
            g_ptr[idx] = run;
            g_ofs[idx] = run;
            run += g_cnt[idx];
        }
    }
    if (t == 0) g_ptr[NN] = ETOT;
}

__global__ void k_scatter(const int* __restrict__ src, const int* __restrict__ dst)
{
    int e = blockIdx.x * blockDim.x + threadIdx.x;
    if (e >= ETOT) return;
    int s, t;
    if (e < EE) { s = src[e]; t = dst[e]; }
    else        { s = t = e - EE; }
    int pos = atomicAdd(&g_ofs[t], 1);
    g_csrc[pos] = s;
}

// =========================== K1: encoders + fusion ===========================
// padded transposed weights: ew2T [128][65], fwT [64][65]
#define ENC_SMEM_F (576 + 8320 + 4160 + 4 * 196)
__global__ void k_encode(const float* __restrict__ xin,
                         const float* __restrict__ ew1, const float* __restrict__ eb1,
                         const float* __restrict__ ew2, const float* __restrict__ eb2,
                         const float* __restrict__ fw,  const float* __restrict__ fb,
                         float* __restrict__ z_out)
{
    extern __shared__ float sm[];
    float* s_ew1  = sm;            // 128
    float* s_eb1  = sm + 128;      // 128
    float* s_eb2  = sm + 256;      // 256
    float* s_fb   = sm + 512;      // 64
    float* s_ew2T = sm + 576;      // 8320: [(m*32+j)*65 + d]
    float* s_fwT  = sm + 8896;     // 4160: [k*65 + d]
    float* s_grp  = sm + 13056;    // 4 * 196

    int tid = threadIdx.x;
    int g = tid >> 6, lt = tid & 63;
    for (int i = tid; i < 128; i += 256) { s_ew1[i] = ew1[i]; s_eb1[i] = eb1[i]; }
    for (int i = tid; i < 256; i += 256) s_eb2[i] = eb2[i];
    if (tid < 64) s_fb[tid] = fb[tid];
    for (int i = tid; i < 8192; i += 256) {
        int m = i >> 11, rem = i & 2047, d = rem >> 5, j = rem & 31;
        s_ew2T[(m * 32 + j) * 65 + d] = ew2[i];
    }
    for (int i = tid; i < 4096; i += 256) {
        int d = i >> 6, k = i & 63;
        s_fwT[k * 65 + d] = fw[i];
    }
    __syncthreads();

    float* sx  = s_grp + g * 196;
    float* sh  = sx + 4;
    float* szm = sx + 132;

    for (int it = 0; it < 16; it++) {
        int n = blockIdx.x * 64 + it * 4 + g;
        bool valid = (n < NN);
        if (valid && lt < 4) sx[lt] = xin[n * MM + lt];
        __syncthreads();
        if (valid) {
            #pragma unroll
            for (int r = 0; r < 2; r++) {
                int idx = lt + 64 * r;
                int m = idx >> 5;
                sh[idx] = gelu_exact(sx[m] * s_ew1[idx] + s_eb1[idx]);
            }
        }
        __syncthreads();
        if (valid) {
            float zm = 0.f;
            #pragma unroll
            for (int m = 0; m < MM; m++) {
                float acc = s_eb2[m * 64 + lt];
                #pragma unroll
                for (int j = 0; j < 32; j++)
                    acc += sh[m * 32 + j] * s_ew2T[(m * 32 + j) * 65 + lt];
                z_out[(size_t)n * 256 + m * 64 + lt] = acc;
                zm += acc;
            }
            szm[lt] = zm * 0.25f;
        }
        __syncthreads();
        if (valid) {
            float acc = s_fb[lt];
            #pragma unroll
            for (int k = 0; k < 64; k++) acc += szm[k] * s_fwT[k * 65 + lt];
            g_x[0][n * 64 + lt] = acc;
        }
        __syncthreads();
    }
}

// =========================== K2: GAT linears (64 nodes/block) ================
// padded: swl/swr [64][257]
#define LIN_SMEM_F (16448 * 2 + 4096)
__global__ void k_lin(int xsel,
                      const float* __restrict__ wl, const float* __restrict__ bl,
                      const float* __restrict__ wr, const float* __restrict__ br)
{
    extern __shared__ float sm[];
    float* swl = sm;              // [k*257 + o]
    float* swr = sm + 16448;
    float* sx  = sm + 32896;      // 64x64
    int tid = threadIdx.x;
    int nb = blockIdx.x * 64;
    for (int i = tid; i < 16384; i += 256) {
        int o = i >> 6, k = i & 63;
        swl[k * 257 + o] = wl[i];
        swr[k * 257 + o] = wr[i];
    }
    const float* xsrc = g_x[xsel] + (size_t)nb * 64;
    for (int i = tid; i < 4096; i += 256) sx[i] = xsrc[i];
    __syncthreads();

    int o = tid;
    float blv = bl[o], brv = br[o];
    #pragma unroll
    for (int c = 0; c < 8; c++) {
        float aL[8], aR[8];
        #pragma unroll
        for (int i = 0; i < 8; i++) { aL[i] = 0.f; aR[i] = 0.f; }
        for (int k = 0; k < 64; k++) {
            float w1 = swl[k * 257 + o];
            float w2 = swr[k * 257 + o];
            #pragma unroll
            for (int i = 0; i < 8; i++) {
                float xv = sx[(c * 8 + i) * 64 + k];
                aL[i] += xv * w1;
                aR[i] += xv * w2;
            }
        }
        #pragma unroll
        for (int i = 0; i < 8; i++) {
            size_t row = (size_t)(nb + c * 8 + i) * FF;
            g_xl[row + o] = aL[i] + blv;
            g_xr[row + o] = aR[i] + brv;
        }
    }
}

// =========================== K3: fused GAT edge phase ========================
// one warp per destination node; online softmax; unrolled by 2 (states A/B).
#define GAT_EDGE(idx, M_, DEN_, A0x,A0y,A0z,A0w, A1x,A1y,A1z,A1w)              \
    {                                                                          \
        int s_ = g_csrc[idx];                                                  \
        const float4* xl4_ = (const float4*)(g_xl + (size_t)s_ * FF);          \
        float4 l0 = xl4_[lane * 2];                                            \
        float4 l1 = xl4_[lane * 2 + 1];                                        \
        float p = 0.f, e_;                                                     \
        e_ = l0.x + xr0.x; p += (e_ > 0.f ? e_ : 0.2f * e_) * av0.x;           \
        e_ = l0.y + xr0.y; p += (e_ > 0.f ? e_ : 0.2f * e_) * av0.y;           \
        e_ = l0.z + xr0.z; p += (e_ > 0.f ? e_ : 0.2f * e_) * av0.z;           \
        e_ = l0.w + xr0.w; p += (e_ > 0.f ? e_ : 0.2f * e_) * av0.w;           \
        e_ = l1.x + xr1.x; p += (e_ > 0.f ? e_ : 0.2f * e_) * av1.x;           \
        e_ = l1.y + xr1.y; p += (e_ > 0.f ? e_ : 0.2f * e_) * av1.y;           \
        e_ = l1.z + xr1.z; p += (e_ > 0.f ? e_ : 0.2f * e_) * av1.z;           \
        e_ = l1.w + xr1.w; p += (e_ > 0.f ? e_ : 0.2f * e_) * av1.w;           \
        p += __shfl_xor_sync(0xffffffffu, p, 1);                               \
        p += __shfl_xor_sync(0xffffffffu, p, 2);                               \
        p += __shfl_xor_sync(0xffffffffu, p, 4);                               \
        float mn_ = fmaxf(M_, p);                                              \
        float cr_ = __expf(M_ - mn_);                                          \
        float pe_ = __expf(p - mn_);                                           \
        DEN_ = DEN_ * cr_ + pe_;                                               \
        A0x = A0x * cr_ + pe_ * l0.x; A0y = A0y * cr_ + pe_ * l0.y;            \
        A0z = A0z * cr_ + pe_ * l0.z; A0w = A0w * cr_ + pe_ * l0.w;            \
        A1x = A1x * cr_ + pe_ * l1.x; A1y = A1y * cr_ + pe_ * l1.y;            \
        A1z = A1z * cr_ + pe_ * l1.z; A1w = A1w * cr_ + pe_ * l1.w;            \
        M_ = mn_;                                                              \
    }

__global__ void k_gat(const float* __restrict__ att, const float* __restrict__ bias,
                      int xsel, int dsel)
{
    int node = blockIdx.x * 8 + (threadIdx.x >> 5);
    if (node >= NN) return;
    int lane = threadIdx.x & 31;

    const float4* xr4 = (const float4*)(g_xr + (size_t)node * FF);
    float4 xr0 = xr4[lane * 2];
    float4 xr1 = xr4[lane * 2 + 1];
    const float4* a4 = (const float4*)att;
    float4 av0 = a4[lane * 2];
    float4 av1 = a4[lane * 2 + 1];

    float mA = -FLT_MAX, dA = 0.f;
    float a0x = 0.f, a0y = 0.f, a0z = 0.f, a0w = 0.f;
    float a1x = 0.f, a1y = 0.f, a1z = 0.f, a1w = 0.f;
    float mB = -FLT_MAX, dB = 0.f;
    float b0x = 0.f, b0y = 0.f, b0z = 0.f, b0w = 0.f;
    float b1x = 0.f, b1y = 0.f, b1z = 0.f, b1w = 0.f;

    int beg = g_ptr[node], end = g_ptr[node + 1];
    int i = beg;
    for (; i + 1 < end; i += 2) {
        GAT_EDGE(i,     mA, dA, a0x,a0y,a0z,a0w, a1x,a1y,a1z,a1w)
        GAT_EDGE(i + 1, mB, dB, b0x,b0y,b0z,b0w, b1x,b1y,b1z,b1w)
    }
    if (i < end) {
        GAT_EDGE(i, mA, dA, a0x,a0y,a0z,a0w, a1x,a1y,a1z,a1w)
    }

    // merge B into A (B may be empty: dB == 0, mB == -FLT_MAX)
    float den, v0x,v0y,v0z,v0w, v1x,v1y,v1z,v1w;
    if (dB > 0.f) {
        float mn = fmaxf(mA, mB);
        float cA = __expf(mA - mn);
        float cB = __expf(mB - mn);
        den = dA * cA + dB * cB;
        v0x = a0x * cA + b0x * cB; v0y = a0y * cA + b0y * cB;
        v0z = a0z * cA + b0z * cB; v0w = a0w * cA + b0w * cB;
        v1x = a1x * cA + b1x * cB; v1y = a1y * cA + b1y * cB;
        v1z = a1z * cA + b1z * cB; v1w = a1w * cA + b1w * cB;
    } else {
        den = dA;
        v0x = a0x; v0y = a0y; v0z = a0z; v0w = a0w;
        v1x = a1x; v1y = a1y; v1z = a1z; v1w = a1w;
    }

    float inv = 1.f / (den + 1e-16f);
    float v[8];
    v[0] = v0x * inv; v[1] = v0y * inv; v[2] = v0z * inv; v[3] = v0w * inv;
    v[4] = v1x * inv; v[5] = v1y * inv; v[6] = v1z * inv; v[7] = v1w * inv;
    #pragma unroll
    for (int q = 0; q < 8; q++) {
        v[q] += __shfl_xor_sync(0xffffffffu, v[q], 8);
        v[q] += __shfl_xor_sync(0xffffffffu, v[q], 16);
    }
    if (lane < 8) {
        float o[8];
        const float* bs = bias + lane * 8;
        #pragma unroll
        for (int q = 0; q < 8; q++)
            o[q] = gelu_exact(0.25f * v[q] + bs[q]);
        float4* dst4 = (float4*)(g_x[dsel] + (size_t)node * DD + lane * 8);
        dst4[0] = make_float4(o[0], o[1], o[2], o[3]);
        dst4[1] = make_float4(o[4], o[5], o[6], o[7]);
    }
}

// =========================== K7: fusion + heads ==============================
// padded: qwT [64][65], kwT [256][65], rw1T/uw1T [64][33]
#define HEAD_GRP_F 772
#define HEAD_SMEM_F (4160 + 16640 + 2112 + 2112 + 450 + 4 * HEAD_GRP_F)
__global__ void k_head(int xsel, const float* __restrict__ z,
                       const float* __restrict__ qw, const float* __restrict__ qb,
                       const float* __restrict__ kw, const float* __restrict__ kb,
                       const float* __restrict__ rw1, const float* __restrict__ rb1,
                       const float* __restrict__ rw2, const float* __restrict__ rb2,
                       const float* __restrict__ uw1, const float* __restrict__ ub1,
                       const float* __restrict__ uw2, const float* __restrict__ ub2,
                       float* __restrict__ risk, float* __restrict__ unc,
                       float* __restrict__ attn)
{
    extern __shared__ float sm[];
    float* s_qwT  = sm;                  // 4160:  [k*65 + d]
    float* s_kwT  = sm + 4160;           // 16640: [(m*64+k)*65 + e]
    float* s_rw1T = sm + 20800;          // 2112:  [k*33 + j]
    float* s_uw1T = sm + 22912;          // 2112
    float* s_rw2  = sm + 25024;          // 32
    float* s_uw2  = sm + 25056;          // 32
    float* s_qb   = sm + 25088;          // 64
    float* s_kb   = sm + 25152;          // 256
    float* s_rb1  = sm + 25408;          // 32
    float* s_ub1  = sm + 25440;          // 32
    float* s_sc2  = sm + 25472;          // 2
    float* s_grp  = sm + 25474;

    int tid = threadIdx.x;
    int g = tid >> 6, lt = tid & 63;

    for (int i = tid; i < 4096; i += 256) {
        int d = i >> 6, k = i & 63;
        s_qwT[k * 65 + d] = qw[i];
    }
    for (int i = tid; i < 16384; i += 256) {
        int m = i >> 12, rem = i & 4095, e = rem >> 6, k = rem & 63;
        s_kwT[(m * 64 + k) * 65 + e] = kw[i];
    }
    for (int i = tid; i < 2048; i += 256) {
        int j = i >> 6, k = i & 63;
        s_rw1T[k * 33 + j] = rw1[i];
        s_uw1T[k * 33 + j] = uw1[i];
    }
    if (tid < 32) { s_rw2[tid] = rw2[tid]; s_uw2[tid] = uw2[tid]; }
    if (tid < 64) s_qb[tid] = qb[tid];
    for (int i = tid; i < 256; i += 256) s_kb[i] = kb[i];
    if (tid < 32) { s_rb1[tid] = rb1[tid]; s_ub1[tid] = ub1[tid]; }
    if (tid == 0) { s_sc2[0] = rb2[0]; s_sc2[1] = ub2[0]; }
    __syncthreads();

    float* xs  = s_grp + g * HEAD_GRP_F;
    float* zs  = xs + 64;
    float* red = xs + 320;
    float* at  = xs + 576;
    float* fu  = xs + 580;
    float* hs  = xs + 644;

    for (int it = 0; it < 16; it++) {
        int n = blockIdx.x * 64 + it * 4 + g;
        bool valid = (n < NN);
        if (valid) {
            xs[lt] = g_x[xsel][n * 64 + lt];
            #pragma unroll
            for (int m = 0; m < MM; m++)
                zs[m * 64 + lt] = z[(size_t)n * 256 + m * 64 + lt];
        }
        __syncthreads();
        if (valid) {
            float acc = s_qb[lt];
            #pragma unroll
            for (int k = 0; k < 64; k++) acc += xs[k] * s_qwT[k * 65 + lt];
            float qv = acc;
            #pragma unroll
            for (int m = 0; m < MM; m++) {
                float a2 = s_kb[m * 64 + lt];
                #pragma unroll
                for (int k = 0; k < 64; k++)
                    a2 += zs[m * 64 + k] * s_kwT[(m * 64 + k) * 65 + lt];
                red[m * 64 + lt] = a2 * qv;
            }
        }
        __syncthreads();
        if (valid && lt < MM) {
            float s = 0.f;
            #pragma unroll
            for (int k = 0; k < 64; k++) s += red[lt * 64 + k];
            at[lt] = s * 0.125f;
        }
        __syncthreads();
        if (valid && lt == 0) {
            float mx = fmaxf(fmaxf(at[0], at[1]), fmaxf(at[2], at[3]));
            float sum = 0.f;
            #pragma unroll
            for (int m = 0; m < MM; m++) { at[m] = expf(at[m] - mx); sum += at[m]; }
            float iv = 1.f / sum;
            #pragma unroll
            for (int m = 0; m < MM; m++) { at[m] *= iv; attn[n * MM + m] = at[m]; }
        }
        __syncthreads();
        if (valid) {
            float acc = 0.f;
            #pragma unroll
            for (int m = 0; m < MM; m++) acc += at[m] * zs[m * 64 + lt];
            fu[lt] = acc;
        }
        __syncthreads();
        if (valid) {
            if (lt < 32) {
                float acc = s_rb1[lt];
                #pragma unroll
                for (int k = 0; k < 64; k++) acc += fu[k] * s_rw1T[k * 33 + lt];
                hs[lt] = gelu_exact(acc);
            } else {
                int j = lt - 32;
                float acc = s_ub1[j];
                #pragma unroll
                for (int k = 0; k < 64; k++) acc += fu[k] * s_uw1T[k * 33 + j];
                hs[lt] = gelu_exact(acc);
            }
        }
        __syncthreads();
        if (valid && lt == 0) {
            float acc = s_sc2[0];
            #pragma unroll
            for (int j = 0; j < 32; j++) acc += hs[j] * s_rw2[j];
            risk[n] = acc;
        }
        if (valid && lt == 1) {
            float acc = s_sc2[1];
            #pragma unroll
            for (int j = 0; j < 32; j++) acc += hs[32 + j] * s_uw2[j];
            unc[n] = 1.f / (1.f + expf(-acc));
        }
        __syncthreads();
    }
}

// =========================== launch ==========================================
extern "C" void kernel_launch(void* const* d_in, const int* in_sizes, int n_in,
                              void* d_out, int out_size)
{
    const float* xmm  = (const float*)d_in[0];
    const int*   ei   = (const int*)  d_in[1];
    const float* ew1  = (const float*)d_in[2];
    const float* eb1  = (const float*)d_in[3];
    const float* ew2  = (const float*)d_in[4];
    const float* eb2  = (const float*)d_in[5];
    const float* fw   = (const float*)d_in[6];
    const float* fb   = (const float*)d_in[7];
    const float* gwl  = (const float*)d_in[8];
    const float* gbl  = (const float*)d_in[9];
    const float* gwr  = (const float*)d_in[10];
    const float* gbr  = (const float*)d_in[11];
    const float* gatt = (const float*)d_in[12];
    const float* gbia = (const float*)d_in[13];
    const float* qw   = (const float*)d_in[14];
    const float* qb   = (const float*)d_in[15];
    const float* kw   = (const float*)d_in[16];
    const float* kb   = (const float*)d_in[17];
    const float* rw1  = (const float*)d_in[18];
    const float* rb1  = (const float*)d_in[19];
    const float* rw2  = (const float*)d_in[20];
    const float* rb2  = (const float*)d_in[21];
    const float* uw1  = (const float*)d_in[22];
    const float* ub1  = (const float*)d_in[23];
    const float* uw2  = (const float*)d_in[24];
    const float* ub2  = (const float*)d_in[25];

    float* out    = (float*)d_out;
    float* o_risk = out;
    float* o_unc  = out + NN;
    float* o_attn = out + 2 * NN;
    float* o_z    = out + 2 * NN + NN * MM;

    const int* src = ei;
    const int* dst = ei + EE;

    cudaFuncSetAttribute(k_encode, cudaFuncAttributeMaxDynamicSharedMemorySize,
                         ENC_SMEM_F * 4);
    cudaFuncSetAttribute(k_lin, cudaFuncAttributeMaxDynamicSharedMemorySize,
                         LIN_SMEM_F * 4);
    cudaFuncSetAttribute(k_head, cudaFuncAttributeMaxDynamicSharedMemorySize,
                         HEAD_SMEM_F * 4);

    // CSR build (edge set is layer-independent)
    k_zero<<<(NN + 255) / 256, 256>>>();
    k_count<<<(ETOT + 255) / 256, 256>>>(dst);
    k_scan<<<1, 1024>>>();
    k_scatter<<<(ETOT + 255) / 256, 256>>>(src, dst);

    k_encode<<<(NN + 63) / 64, 256, ENC_SMEM_F * 4>>>(xmm, ew1, eb1, ew2, eb2,
                                                      fw, fb, o_z);

    int cur = 0;
    for (int l = 0; l < NLL; l++) {
        k_lin<<<(NN + 63) / 64, 256, LIN_SMEM_F * 4>>>(cur,
                               gwl + (size_t)l * FF * DD, gbl + l * FF,
                               gwr + (size_t)l * FF * DD, gbr + l * FF);
        k_gat<<<(NN + 7) / 8, 256>>>(gatt + l * NHH * DD, gbia + l * DD,
                                     cur, cur ^ 1);
        cur ^= 1;
    }

    k_head<<<(NN + 63) / 64, 256, HEAD_SMEM_F * 4>>>(cur, o_z, qw, qb, kw, kb,
                       rw1, rb1, rw2, rb2, uw1, ub1, uw2, ub2,
                       o_risk, o_unc, o_attn);
}